// round 13
// baseline (speedup 1.0000x reference)
#include <cuda_runtime.h>
#include <cuda_fp16.h>
#include <cstdint>

#define N_TOK 8192
#define DIM   1024
#define NEXP  8
#define CAP   1024
#define SCAN_BLOCKS 8
#define TILES_PER_EXPERT 64   // 8x8 tiles of 128x128
#define NDISP 512             // dispatch blocks, 16 slots each
#define DISP0 SCAN_BLOCKS
#define G1_0  (DISP0 + NDISP)
#define G2_0  (G1_0 + NEXP * TILES_PER_EXPERT)
#define NBLK  (G2_0 + NEXP * TILES_PER_EXPERT)

// ---------------- scratch (device globals; no allocation allowed) ----------
__device__ __half g_Ah[(size_t)N_TOK * DIM];   // expert_in fp16
__device__ __half g_Hh[(size_t)N_TOK * DIM];   // hidden fp16
__device__ __half g_B1h[(size_t)N_TOK * DIM];  // W1^T fp16 [e][n][k]
__device__ __half g_B2h[(size_t)N_TOK * DIM];  // W2^T fp16
__device__ int   g_idx[N_TOK];
__device__ float g_gate[N_TOK];
__device__ int   g_comb[N_TOK];
__device__ int   g_tok[NEXP * CAP];
__device__ unsigned long long g_agg0[SCAN_BLOCKS], g_agg1[SCAN_BLOCKS];
__device__ int   g_flag[SCAN_BLOCKS];
__device__ int   g_sdone;                      // scan blocks completed
__device__ int   g_disp[NEXP];                 // dispatch blocks per expert
__device__ int   g_done[NEXP];                 // GEMM1 tiles per expert

// ---------------- PTX helpers (sm_80-level only) -----------------------------
__device__ __forceinline__ uint32_t smem_u32(const void* p) {
    uint32_t a;
    asm("{ .reg .u64 t; cvta.to.shared.u64 t, %1; cvt.u32.u64 %0, t; }"
        : "=r"(a) : "l"(p));
    return a;
}

#define CP_ASYNC16(dst, src) \
    asm volatile("cp.async.cg.shared.global [%0], [%1], 16;" :: "r"(dst), "l"(src) : "memory")
#define CP_COMMIT() asm volatile("cp.async.commit_group;" ::: "memory")
#define CP_WAIT1()  asm volatile("cp.async.wait_group 1;" ::: "memory")

#define LDSM_X4(r, addr) \
    asm volatile("ldmatrix.sync.aligned.m8n8.x4.shared.b16 {%0,%1,%2,%3}, [%4];" \
        : "=r"((r)[0]), "=r"((r)[1]), "=r"((r)[2]), "=r"((r)[3]) : "r"(addr))

#define MMA_FP16(d, a, b) \
    asm volatile("mma.sync.aligned.m16n8k16.row.col.f32.f16.f16.f32 " \
        "{%0,%1,%2,%3}, {%4,%5,%6,%7}, {%8,%9}, {%0,%1,%2,%3};" \
        : "+f"((d)[0]), "+f"((d)[1]), "+f"((d)[2]), "+f"((d)[3]) \
        : "r"((a)[0]), "r"((a)[1]), "r"((a)[2]), "r"((a)[3]), \
          "r"((b)[0]), "r"((b)[1]))

__device__ __forceinline__ uint32_t pk(__half a, __half b) {
    return (uint32_t)__half_as_ushort(a) | ((uint32_t)__half_as_ushort(b) << 16);
}

// ---------------- router (+ all counter/table init fused) --------------------
__global__ void router_kernel(const float* __restrict__ x,
                              const float* __restrict__ Wr,
                              const float* __restrict__ br) {
    int gid = blockIdx.x * blockDim.x + threadIdx.x;
    if (gid < NEXP * CAP) g_tok[gid] = -1;
    if (gid < SCAN_BLOCKS) g_flag[gid] = 0;
    if (gid >= 8 && gid < 8 + NEXP) g_done[gid - 8] = 0;
    if (gid >= 16 && gid < 16 + NEXP) g_disp[gid - 16] = 0;
    if (gid == 24) g_sdone = 0;
    int gwarp = gid >> 5;
    int lane  = threadIdx.x & 31;
    if (gwarp >= N_TOK) return;
    const float* xr = x + (size_t)gwarp * DIM;
    float acc[NEXP];
#pragma unroll
    for (int e = 0; e < NEXP; e++) acc[e] = 0.f;
    for (int d = lane; d < DIM; d += 32) {
        float xv = xr[d];
        const float* w = Wr + d * NEXP;
#pragma unroll
        for (int e = 0; e < NEXP; e++) acc[e] += xv * w[e];
    }
#pragma unroll
    for (int o = 16; o > 0; o >>= 1)
#pragma unroll
        for (int e = 0; e < NEXP; e++)
            acc[e] += __shfl_xor_sync(0xffffffffu, acc[e], o);
    if (lane == 0) {
        float m = -1e30f; int ai = 0;
#pragma unroll
        for (int e = 0; e < NEXP; e++) {
            acc[e] += br[e];
            if (acc[e] > m) { m = acc[e]; ai = e; }   // strict > keeps first
        }
        float s = 0.f;
#pragma unroll
        for (int e = 0; e < NEXP; e++) s += expf(acc[e] - m);
        g_idx[gwarp]  = ai;
        g_gate[gwarp] = 1.f / s;
    }
}

// ---------------- weight transpose fp32[k][n] -> fp16[n][k], 64x64 tiles -----
__global__ void __launch_bounds__(256) wt_kernel(const float* __restrict__ W,
                                                 __half* __restrict__ Bh) {
    __shared__ float ts[64][65];
    int e = blockIdx.z;
    int k0 = blockIdx.y * 64, n0 = blockIdx.x * 64;
    int t = threadIdx.x;
    const float* Wb = W + (size_t)e * DIM * DIM;
    int lr = t >> 4, lc = (t & 15) * 4;
#pragma unroll
    for (int i = 0; i < 4; i++) {
        int kr = lr + i * 16;
        float4 v = *reinterpret_cast<const float4*>(Wb + (size_t)(k0 + kr) * DIM + n0 + lc);
        ts[kr][lc + 0] = v.x; ts[kr][lc + 1] = v.y;
        ts[kr][lc + 2] = v.z; ts[kr][lc + 3] = v.w;
    }
    __syncthreads();
    int r  = t >> 2;             // n within tile
    int kk = (t & 3) * 16;       // k start
    uint32_t w[8];
#pragma unroll
    for (int q = 0; q < 8; q++)
        w[q] = pk(__float2half_rn(ts[kk + 2 * q][r]), __float2half_rn(ts[kk + 2 * q + 1][r]));
    size_t o = (size_t)e * DIM * DIM + (size_t)(n0 + r) * DIM + k0 + kk;
    *reinterpret_cast<uint4*>(Bh + o)     = make_uint4(w[0], w[1], w[2], w[3]);
    *reinterpret_cast<uint4*>(Bh + o + 8) = make_uint4(w[4], w[5], w[6], w[7]);
}

// ======== MEGA KERNEL: scan + dispatch + GEMM1 + GEMM2, spin-chained =========
// bids [0,8):          scan (256 thr, 4 tokens/thr, chained cross-block prefix)
// bids [8,520):        dispatch 16 slots each; spins g_sdone==8; bumps g_disp[ex]
// bids [520,1032):     GEMM1 tile; spins g_disp[ex]==64; bumps g_done[ex]
// bids [1032,1544):    GEMM2 tile; spins g_done[ex]==64
// Every spin targets strictly-lower bids; CWD dispatches ascending bid =>
// the lowest incomplete bid can always progress => deadlock-free.
#define STAGES  3
#define TILEB   16384             // 128 rows x 128B
#define NPLANES 2
#define STAGEB  (NPLANES * TILEB)
#define NCHUNK  16                // K=1024 / BK=64
#define GEMM_SMEM (2048 + STAGES * STAGEB)

// SW128 swizzle for 128B rows: seg(0..7) ^= row&7
#define SWZ128(row, seg) ((row) * 128 + (((seg) ^ ((row) & 7)) << 4))

__global__ void __launch_bounds__(256, 2) moe_fused(
    const float* __restrict__ x,
    const __half* __restrict__ B1h, const float* __restrict__ b1,
    const __half* __restrict__ B2h, const float* __restrict__ b2,
    float* __restrict__ out) {
    const int tid = threadIdx.x;
    const int bid = blockIdx.x;

    // ---------------- phase S: scan ----------------
    if (bid < DISP0) {
        __shared__ unsigned long long w0s[8], w1s[8];
        __shared__ unsigned long long prev0s, prev1s;
        int b = bid;
        int lane = tid & 31, wp = tid >> 5;   // 8 warps
        int4 v = reinterpret_cast<const int4*>(g_idx)[b * 256 + tid];
        int e4[4] = {v.x, v.y, v.z, v.w};
        unsigned long long c0 = 0ull, c1 = 0ull;
#pragma unroll
        for (int i = 0; i < 4; i++) {
            int e = e4[i];
            if (e < 4) c0 += 1ull << (16 * e);
            else       c1 += 1ull << (16 * (e - 4));
        }
        unsigned long long s0 = c0, s1 = c1;
#pragma unroll
        for (int o = 1; o < 32; o <<= 1) {
            unsigned long long t0 = __shfl_up_sync(0xffffffffu, s0, o);
            unsigned long long t1 = __shfl_up_sync(0xffffffffu, s1, o);
            if (lane >= o) { s0 += t0; s1 += t1; }
        }
        if (lane == 31) { w0s[wp] = s0; w1s[wp] = s1; }
        __syncthreads();
        if (tid == 0) {
            unsigned long long a0 = 0ull, a1 = 0ull;
#pragma unroll
            for (int w = 0; w < 8; w++) {       // exclusive warp prefixes + totals
                unsigned long long t0 = w0s[w], t1 = w1s[w];
                w0s[w] = a0; w1s[w] = a1;
                a0 += t0; a1 += t1;
            }
            unsigned long long p0 = 0ull, p1 = 0ull;
            if (b > 0) {
                while (atomicAdd(&g_flag[b - 1], 0) == 0) { }
                __threadfence();
                p0 = g_agg0[b - 1]; p1 = g_agg1[b - 1];
            }
            prev0s = p0; prev1s = p1;
            g_agg0[b] = p0 + a0; g_agg1[b] = p1 + a1;
            __threadfence();
            atomicExch(&g_flag[b], 1);
        }
        __syncthreads();
        unsigned long long p0 = prev0s + w0s[wp] + (s0 - c0);  // exclusive
        unsigned long long p1 = prev1s + w1s[wp] + (s1 - c1);
#pragma unroll
        for (int i = 0; i < 4; i++) {
            int n = b * 1024 + tid * 4 + i, e = e4[i];
            int pos;
            if (e < 4) { p0 += 1ull << (16 * e);       pos = (int)((p0 >> (16 * e)) & 0xFFFFull); }
            else       { p1 += 1ull << (16 * (e - 4)); pos = (int)((p1 >> (16 * (e - 4))) & 0xFFFFull); }
            if (pos < CAP) {
                g_comb[n] = e * CAP + pos;       // 1-based pos, slot 0 unused
                g_tok[e * CAP + pos] = n;
            } else {
                g_comb[n] = -1;
            }
        }
        __threadfence();
        __syncthreads();
        if (tid == 0) atomicAdd(&g_sdone, 1);
        return;
    }

    // ---------------- phase D: dispatch + dropzero ----------------
    if (bid < G1_0) {
        int db = bid - DISP0;        // 0..511
        if (tid == 0)
            while (atomicAdd(&g_sdone, 0) < SCAN_BLOCKS) { }
        __syncthreads();
        __threadfence();
        int ex = db >> 6;
#pragma unroll
        for (int i = 0; i < 16; i++) {
            int s = db * 16 + i;
            int n = g_tok[s];
            uint2* dh = reinterpret_cast<uint2*>(g_Ah + (size_t)s * DIM) + tid;
            if (n < 0) {
                *dh = make_uint2(0u, 0u);
            } else {
                float g = g_gate[n];
                float4 v = reinterpret_cast<const float4*>(x + (size_t)n * DIM)[tid];
                *dh = make_uint2(pk(__float2half_rn(v.x * g), __float2half_rn(v.y * g)),
                                 pk(__float2half_rn(v.z * g), __float2half_rn(v.w * g)));
            }
        }
#pragma unroll
        for (int i = 0; i < 16; i++) {
            int n = db * 16 + i;
            if (g_comb[n] < 0)
                reinterpret_cast<float4*>(out + (size_t)n * DIM)[tid] =
                    make_float4(0.f, 0.f, 0.f, 0.f);
        }
        __threadfence();
        __syncthreads();
        if (tid == 0) atomicAdd(&g_disp[ex], 1);
        return;
    }

    // ---------------- phases G1 / G2: GEMM tiles ----------------
    extern __shared__ char smem[];
    uint32_t raw = smem_u32(smem);
    uint32_t tiles = (raw + 512 + 1023) & ~1023u;
    float* sb = reinterpret_cast<float*>(smem + (tiles - 512 - raw)); // 128 floats

    const int lane = tid & 31, wid = tid >> 5;
    const bool phase2 = bid >= G2_0;
    const int lb = bid - (phase2 ? G2_0 : G1_0);
    const int ex = lb >> 6;
    const int tl = lb & 63;
    const int bx = tl & 7, by = tl >> 3;

    if (tid == 0) {
        if (phase2) while (atomicAdd(&g_done[ex], 0) < TILES_PER_EXPERT) { }
        else        while (atomicAdd(&g_disp[ex], 0) < TILES_PER_EXPERT) { }
    }
    __syncthreads();
    __threadfence();

    const __half* Ain  = phase2 ? g_Hh : g_Ah;
    const __half* Bin  = phase2 ? B2h  : B1h;
    const float*  bias = phase2 ? b2   : b1;

    const size_t rowA0 = (size_t)ex * 1024 + (size_t)by * 128;
    const size_t rowB0 = (size_t)ex * 1024 + (size_t)bx * 128;
    const char* pA[2] = {
        (const char*)(Ain + rowA0 * DIM), (const char*)(Bin + rowB0 * DIM)};

    if (tid < 128) sb[tid] = bias[ex * DIM + bx * 128 + tid];

    auto load_chunk = [&](int c, int s) {
        uint32_t st = tiles + s * STAGEB;
        int kb = c * 128;  // 64 fp16 = 128B per row-chunk
#pragma unroll
        for (int i = 0; i < 8; i++) {
            int g = tid + i * 256;        // 0..2047
            int tile = g >> 10;
            int j = g & 1023;
            int row = j >> 3, seg = j & 7;
            uint32_t dst = st + tile * TILEB + SWZ128(row, seg);
            const char* src = pA[tile] + (size_t)row * (DIM * 2) + kb + seg * 16;
            CP_ASYNC16(dst, src);
        }
    };

    load_chunk(0, 0); CP_COMMIT();
    load_chunk(1, 1); CP_COMMIT();

    float acc[4][4][4];
#pragma unroll
    for (int i = 0; i < 4; i++)
#pragma unroll
        for (int j = 0; j < 4; j++)
#pragma unroll
            for (int q = 0; q < 4; q++) acc[i][j][q] = 0.f;

    const int m_off = (wid & 1) * 64;    // warp tile 64x32; warps 2x4
    const int n_off = (wid >> 1) * 32;
    const int grp = lane >> 3, loc = lane & 7;
    const int rowoff_a = (grp & 1) * 8 + loc;
    const int segoff_a = grp >> 1;
    const int rowoff_b = (grp >> 1) * 8 + loc;
    const int segoff_b = grp & 1;

    for (int c = 0; c < NCHUNK; c++) {
        int s = c % STAGES;
        CP_WAIT1();                 // chunk c resident (c+1 still in flight)
        __syncthreads();            // WAR: all warps done reading stage (c+2)%3
        if (c + 2 < NCHUNK) load_chunk(c + 2, (c + 2) % STAGES);
        CP_COMMIT();
        uint32_t st = tiles + s * STAGEB;
#pragma unroll
        for (int ks = 0; ks < 4; ks++) {
            int seg0 = ks * 2;
            uint32_t bH[4][2];
#pragma unroll
            for (int p = 0; p < 2; p++) {
                int row = n_off + p * 16 + rowoff_b;
                int seg = seg0 + segoff_b;
                uint32_t bd = st + TILEB + SWZ128(row, seg);
                uint32_t r[4];
                LDSM_X4(r, bd);
                bH[2 * p][0] = r[0]; bH[2 * p][1] = r[1];
                bH[2 * p + 1][0] = r[2]; bH[2 * p + 1][1] = r[3];
            }
#pragma unroll
            for (int mt = 0; mt < 4; mt++) {
                int row = m_off + mt * 16 + rowoff_a;
                int seg = seg0 + segoff_a;
                uint32_t ad = st + SWZ128(row, seg);
                uint32_t aH[4];
                LDSM_X4(aH, ad);
#pragma unroll
                for (int nt = 0; nt < 4; nt++)
                    MMA_FP16(acc[mt][nt], aH, bH[nt]);
            }
        }
    }

    // ---- epilogue ----
    const int colb = bx * 128;
#pragma unroll
    for (int mt = 0; mt < 4; mt++) {
        size_t slot0 = rowA0 + m_off + mt * 16 + (lane >> 2);
        size_t slot1 = slot0 + 8;
        int tok0 = 0, tok1 = 0;
        float gt0 = 0.f, gt1 = 0.f;
        if (phase2) {
            tok0 = g_tok[slot0];
            tok1 = g_tok[slot1];
            gt0 = (tok0 >= 0) ? g_gate[tok0] : 0.f;
            gt1 = (tok1 >= 0) ? g_gate[tok1] : 0.f;
        }
#pragma unroll
        for (int nt = 0; nt < 4; nt++) {
            int cl = n_off + nt * 8 + 2 * (lane & 3);
            float b0 = sb[cl], b1v = sb[cl + 1];
            float v00 = acc[mt][nt][0] + b0, v01 = acc[mt][nt][1] + b1v;
            float v10 = acc[mt][nt][2] + b0, v11 = acc[mt][nt][3] + b1v;
            if (!phase2) {
                v00 = fmaxf(v00, 0.f); v01 = fmaxf(v01, 0.f);
                v10 = fmaxf(v10, 0.f); v11 = fmaxf(v11, 0.f);
                *reinterpret_cast<uint32_t*>(g_Hh + slot0 * DIM + colb + cl) =
                    pk(__float2half_rn(v00), __float2half_rn(v01));
                *reinterpret_cast<uint32_t*>(g_Hh + slot1 * DIM + colb + cl) =
                    pk(__float2half_rn(v10), __float2half_rn(v11));
            } else {
                if (tok0 >= 0)
                    *reinterpret_cast<float2*>(out + (size_t)tok0 * DIM + colb + cl) =
                        make_float2(gt0 * v00, gt0 * v01);
                if (tok1 >= 0)
                    *reinterpret_cast<float2*>(out + (size_t)tok1 * DIM + colb + cl) =
                        make_float2(gt1 * v10, gt1 * v11);
            }
        }
    }

    if (!phase2) {
        __threadfence();            // g_Hh stores visible before counter bump
        __syncthreads();            // all threads' stores issued
        if (tid == 0) atomicAdd(&g_done[ex], 1);
    }
}

// ---------------- launch -------------------------------------------------------
extern "C" void kernel_launch(void* const* d_in, const int* in_sizes, int n_in,
                              void* d_out, int out_size) {
    const float* x  = (const float*)d_in[0];
    const float* Wr = (const float*)d_in[1];
    const float* br = (const float*)d_in[2];
    const float* W1 = (const float*)d_in[3];
    const float* b1 = (const float*)d_in[4];
    const float* W2 = (const float*)d_in[5];
    const float* b2 = (const float*)d_in[6];
    float* out = (float*)d_out;

    void *pB1h, *pB2h;
    cudaGetSymbolAddress(&pB1h, g_B1h);
    cudaGetSymbolAddress(&pB2h, g_B2h);

    cudaFuncSetAttribute(moe_fused, cudaFuncAttributeMaxDynamicSharedMemorySize, GEMM_SMEM);

    // single side stream + 2 events (round-8 layout: verified delta=0)
    static cudaStream_t s_side = nullptr;
    static cudaEvent_t  ev_root = nullptr, ev_wt = nullptr;
    if (s_side == nullptr) {
        cudaStreamCreateWithFlags(&s_side, cudaStreamNonBlocking);
        cudaEventCreateWithFlags(&ev_root, cudaEventDisableTiming);
        cudaEventCreateWithFlags(&ev_wt,   cudaEventDisableTiming);
    }

    // fork: weight conversion runs concurrently with router
    cudaEventRecord(ev_root, 0);
    cudaStreamWaitEvent(s_side, ev_root, 0);
    dim3 wtg(16, 16, NEXP);
    wt_kernel<<<wtg, 256, 0, s_side>>>(W1, (__half*)pB1h);
    wt_kernel<<<wtg, 256, 0, s_side>>>(W2, (__half*)pB2h);
    cudaEventRecord(ev_wt, s_side);

    // main chain: router (also inits all counters), then the mega kernel
    router_kernel<<<N_TOK * 32 / 256, 256>>>(x, Wr, br);
    cudaStreamWaitEvent(0, ev_wt, 0);   // G1 phase reads converted weights
    moe_fused<<<NBLK, 256, GEMM_SMEM>>>(
        x, (const __half*)pB1h, b1, (const __half*)pB2h, b2, out);
}

// round 14
// speedup vs baseline: 1.0326x; 1.0326x over previous
#include <cuda_runtime.h>
#include <cuda_fp16.h>
#include <cstdint>

#define N_TOK 8192
#define DIM   1024
#define NEXP  8
#define CAP   1024
#define SCAN_BLOCKS 8
#define TILES_PER_EXPERT 64   // 8x8 tiles of 128x128
#define G1_TILES (NEXP * TILES_PER_EXPERT)
#define TOT_TILES (2 * G1_TILES)
#define PERSIST_BLOCKS 304    // ~2 per SM

// ---------------- scratch (device globals; no allocation allowed) ----------
__device__ __half g_Ah[(size_t)N_TOK * DIM];   // expert_in fp16
__device__ __half g_Hh[(size_t)N_TOK * DIM];   // hidden fp16
__device__ __half g_B1h[(size_t)N_TOK * DIM];  // W1^T fp16 [e][n][k]
__device__ __half g_B2h[(size_t)N_TOK * DIM];  // W2^T fp16
__device__ int   g_idx[N_TOK];
__device__ float g_gate[N_TOK];
__device__ int   g_comb[N_TOK];
__device__ int   g_tok[NEXP * CAP];
__device__ unsigned long long g_agg0[SCAN_BLOCKS], g_agg1[SCAN_BLOCKS];
__device__ int   g_flag[SCAN_BLOCKS];
__device__ int   g_done[NEXP];                 // GEMM1 tile completion per expert
__device__ int   g_ctr;                        // persistent tile counter

// ---------------- PTX helpers (sm_80-level only) -----------------------------
__device__ __forceinline__ uint32_t smem_u32(const void* p) {
    uint32_t a;
    asm("{ .reg .u64 t; cvta.to.shared.u64 t, %1; cvt.u32.u64 %0, t; }"
        : "=r"(a) : "l"(p));
    return a;
}

#define CP_ASYNC16(dst, src) \
    asm volatile("cp.async.cg.shared.global [%0], [%1], 16;" :: "r"(dst), "l"(src) : "memory")
#define CP_COMMIT() asm volatile("cp.async.commit_group;" ::: "memory")
#define CP_WAIT1()  asm volatile("cp.async.wait_group 1;" ::: "memory")
#define CP_WAIT0()  asm volatile("cp.async.wait_group 0;" ::: "memory")

#define LDSM_X4(r, addr) \
    asm volatile("ldmatrix.sync.aligned.m8n8.x4.shared.b16 {%0,%1,%2,%3}, [%4];" \
        : "=r"((r)[0]), "=r"((r)[1]), "=r"((r)[2]), "=r"((r)[3]) : "r"(addr))

#define MMA_FP16(d, a, b) \
    asm volatile("mma.sync.aligned.m16n8k16.row.col.f32.f16.f16.f32 " \
        "{%0,%1,%2,%3}, {%4,%5,%6,%7}, {%8,%9}, {%0,%1,%2,%3};" \
        : "+f"((d)[0]), "+f"((d)[1]), "+f"((d)[2]), "+f"((d)[3]) \
        : "r"((a)[0]), "r"((a)[1]), "r"((a)[2]), "r"((a)[3]), \
          "r"((b)[0]), "r"((b)[1]))

__device__ __forceinline__ uint32_t pk(__half a, __half b) {
    return (uint32_t)__half_as_ushort(a) | ((uint32_t)__half_as_ushort(b) << 16);
}

// ---------------- router (+ counter/table init fused) ------------------------
__global__ void router_kernel(const float* __restrict__ x,
                              const float* __restrict__ Wr,
                              const float* __restrict__ br) {
    int gid = blockIdx.x * blockDim.x + threadIdx.x;
    if (gid < NEXP * CAP) g_tok[gid] = -1;
    if (gid < SCAN_BLOCKS) g_flag[gid] = 0;
    if (gid >= 8 && gid < 8 + NEXP) g_done[gid - 8] = 0;
    if (gid == 16) g_ctr = 0;
    int gwarp = gid >> 5;
    int lane  = threadIdx.x & 31;
    if (gwarp >= N_TOK) return;
    const float* xr = x + (size_t)gwarp * DIM;
    float acc[NEXP];
#pragma unroll
    for (int e = 0; e < NEXP; e++) acc[e] = 0.f;
    for (int d = lane; d < DIM; d += 32) {
        float xv = xr[d];
        const float* w = Wr + d * NEXP;
#pragma unroll
        for (int e = 0; e < NEXP; e++) acc[e] += xv * w[e];
    }
#pragma unroll
    for (int o = 16; o > 0; o >>= 1)
#pragma unroll
        for (int e = 0; e < NEXP; e++)
            acc[e] += __shfl_xor_sync(0xffffffffu, acc[e], o);
    if (lane == 0) {
        float m = -1e30f; int ai = 0;
#pragma unroll
        for (int e = 0; e < NEXP; e++) {
            acc[e] += br[e];
            if (acc[e] > m) { m = acc[e]; ai = e; }   // strict > keeps first
        }
        float s = 0.f;
#pragma unroll
        for (int e = 0; e < NEXP; e++) s += expf(acc[e] - m);
        g_idx[gwarp]  = ai;
        g_gate[gwarp] = 1.f / s;
    }
}

// -------- order-preserving scan: 8 blocks, chained cross-block prefix --------
__global__ void __launch_bounds__(1024) scan_kernel() {
    __shared__ unsigned long long w0s[32], w1s[32];
    __shared__ unsigned long long prev0s, prev1s;
    int b = blockIdx.x;
    int tid = threadIdx.x, lane = tid & 31, wp = tid >> 5;
    int n = b * 1024 + tid;
    int e = g_idx[n];
    unsigned long long c0 = (e < 4) ? (1ull << (16 * e)) : 0ull;
    unsigned long long c1 = (e < 4) ? 0ull : (1ull << (16 * (e - 4)));
    unsigned long long s0 = c0, s1 = c1;
#pragma unroll
    for (int o = 1; o < 32; o <<= 1) {
        unsigned long long t0 = __shfl_up_sync(0xffffffffu, s0, o);
        unsigned long long t1 = __shfl_up_sync(0xffffffffu, s1, o);
        if (lane >= o) { s0 += t0; s1 += t1; }
    }
    if (lane == 31) { w0s[wp] = s0; w1s[wp] = s1; }
    __syncthreads();
    if (tid < 32) {
        unsigned long long a0 = w0s[tid], a1 = w1s[tid];
#pragma unroll
        for (int o = 1; o < 32; o <<= 1) {
            unsigned long long t0 = __shfl_up_sync(0xffffffffu, a0, o);
            unsigned long long t1 = __shfl_up_sync(0xffffffffu, a1, o);
            if (tid >= o) { a0 += t0; a1 += t1; }
        }
        w0s[tid] = a0; w1s[tid] = a1;
    }
    __syncthreads();
    if (tid == 0) {
        unsigned long long t0 = w0s[31], t1 = w1s[31];  // block totals
        unsigned long long p0 = 0ull, p1 = 0ull;
        if (b > 0) {
            while (atomicAdd(&g_flag[b - 1], 0) == 0) { }
            __threadfence();
            p0 = g_agg0[b - 1]; p1 = g_agg1[b - 1];
        }
        prev0s = p0; prev1s = p1;
        g_agg0[b] = p0 + t0; g_agg1[b] = p1 + t1;
        __threadfence();
        atomicExch(&g_flag[b], 1);
    }
    __syncthreads();
    unsigned long long i0 = prev0s + (wp ? w0s[wp - 1] : 0ull) + s0;
    unsigned long long i1 = prev1s + (wp ? w1s[wp - 1] : 0ull) + s1;
    int pos = (e < 4) ? (int)((i0 >> (16 * e)) & 0xFFFFull)
                      : (int)((i1 >> (16 * (e - 4))) & 0xFFFFull);
    if (pos < CAP) {
        g_comb[n] = e * CAP + pos;           // 1-based pos, slot 0 unused
        g_tok[e * CAP + pos] = n;
    } else {
        g_comb[n] = -1;
    }
}

// -------- dispatch scatter (gate*x -> fp16) + dropped-token zeroing ----------
__global__ void dispatch_kernel(const float* __restrict__ x,
                                float* __restrict__ out) {
    int b = blockIdx.x;
    int t = threadIdx.x;  // 256 threads x 4 elements
    if (b < NEXP * CAP) {
        int n = g_tok[b];
        uint2* dh = reinterpret_cast<uint2*>(g_Ah + (size_t)b * DIM) + t;
        if (n < 0) {
            *dh = make_uint2(0u, 0u);
        } else {
            float g = g_gate[n];
            float4 v = reinterpret_cast<const float4*>(x + (size_t)n * DIM)[t];
            *dh = make_uint2(pk(__float2half_rn(v.x * g), __float2half_rn(v.y * g)),
                             pk(__float2half_rn(v.z * g), __float2half_rn(v.w * g)));
        }
    } else {
        int n = b - NEXP * CAP;
        if (g_comb[n] < 0)
            reinterpret_cast<float4*>(out + (size_t)n * DIM)[t] =
                make_float4(0.f, 0.f, 0.f, 0.f);
    }
}

// ---------------- weight transpose fp32[k][n] -> fp16[n][k], 64x64 tiles -----
__global__ void __launch_bounds__(256) wt_kernel(const float* __restrict__ W,
                                                 __half* __restrict__ Bh) {
    __shared__ float ts[64][65];
    int e = blockIdx.z;
    int k0 = blockIdx.y * 64, n0 = blockIdx.x * 64;
    int t = threadIdx.x;
    const float* Wb = W + (size_t)e * DIM * DIM;
    int lr = t >> 4, lc = (t & 15) * 4;
#pragma unroll
    for (int i = 0; i < 4; i++) {
        int kr = lr + i * 16;
        float4 v = *reinterpret_cast<const float4*>(Wb + (size_t)(k0 + kr) * DIM + n0 + lc);
        ts[kr][lc + 0] = v.x; ts[kr][lc + 1] = v.y;
        ts[kr][lc + 2] = v.z; ts[kr][lc + 3] = v.w;
    }
    __syncthreads();
    int r  = t >> 2;             // n within tile
    int kk = (t & 3) * 16;       // k start
    uint32_t w[8];
#pragma unroll
    for (int q = 0; q < 8; q++)
        w[q] = pk(__float2half_rn(ts[kk + 2 * q][r]), __float2half_rn(ts[kk + 2 * q + 1][r]));
    size_t o = (size_t)e * DIM * DIM + (size_t)(n0 + r) * DIM + k0 + kk;
    *reinterpret_cast<uint4*>(Bh + o)     = make_uint4(w[0], w[1], w[2], w[3]);
    *reinterpret_cast<uint4*>(Bh + o + 8) = make_uint4(w[4], w[5], w[6], w[7]);
}

// ------ persistent fused GEMM1+GEMM2: work-stealing tiles, per-expert sync ----
// tiles [0,512):    GEMM1: h = relu(A @ W1^T + b1) -> g_Hh, g_done[ex]++
// tiles [512,1024): GEMM2: out[tok] = gate*(h @ W2^T + b2); spins on g_done[ex]
// Work stealing: blocks grab tiles in ascending order; every grabbed GEMM1 tile
// is held by a running block, so phase-2 spins always make progress.
#define STAGES  3
#define TILEB   16384             // 128 rows x 128B
#define NPLANES 2
#define STAGEB  (NPLANES * TILEB)
#define NCHUNK  16                // K=1024 / BK=64
#define GEMM_SMEM (2048 + STAGES * STAGEB)

// SW128 swizzle for 128B rows: seg(0..7) ^= row&7
#define SWZ128(row, seg) ((row) * 128 + (((seg) ^ ((row) & 7)) << 4))

__global__ void __launch_bounds__(256, 2) gemm_persist(
    const __half* __restrict__ B1h, const float* __restrict__ b1,
    const __half* __restrict__ B2h, const float* __restrict__ b2,
    float* __restrict__ out) {
    extern __shared__ char smem[];
    uint32_t raw = smem_u32(smem);
    uint32_t tiles = (raw + 512 + 1023) & ~1023u;
    float* sb = reinterpret_cast<float*>(smem + (tiles - 512 - raw)); // 128 floats
    __shared__ int s_tile;

    const int tid = threadIdx.x;
    const int lane = tid & 31, wid = tid >> 5;

    const int m_off = (wid & 1) * 64;    // warp tile 64x32; warps 2x4
    const int n_off = (wid >> 1) * 32;
    const int grp = lane >> 3, loc = lane & 7;
    const int rowoff_a = (grp & 1) * 8 + loc;
    const int segoff_a = grp >> 1;
    const int rowoff_b = (grp >> 1) * 8 + loc;
    const int segoff_b = grp & 1;

    for (;;) {
        __syncthreads();              // protect sb / smem reuse across iterations
        if (tid == 0) s_tile = atomicAdd(&g_ctr, 1);
        __syncthreads();
        int t = s_tile;
        if (t >= TOT_TILES) return;

        const bool phase2 = t >= G1_TILES;
        const int lb = phase2 ? t - G1_TILES : t;
        const int ex = lb >> 6;
        const int tl = lb & 63;
        const int bx = tl & 7, by = tl >> 3;

        if (phase2) {
            if (tid == 0)
                while (atomicAdd(&g_done[ex], 0) < TILES_PER_EXPERT) { }
            __syncthreads();
            __threadfence();
        }

        const __half* Ain  = phase2 ? g_Hh : g_Ah;
        const __half* Bin  = phase2 ? B2h  : B1h;
        const float*  bias = phase2 ? b2   : b1;

        const size_t rowA0 = (size_t)ex * 1024 + (size_t)by * 128;
        const size_t rowB0 = (size_t)ex * 1024 + (size_t)bx * 128;
        const char* pA[2] = {
            (const char*)(Ain + rowA0 * DIM), (const char*)(Bin + rowB0 * DIM)};

        if (tid < 128) sb[tid] = bias[ex * DIM + bx * 128 + tid];

        auto load_chunk = [&](int c, int s) {
            uint32_t st = tiles + s * STAGEB;
            int kb = c * 128;  // 64 fp16 = 128B per row-chunk
#pragma unroll
            for (int i = 0; i < 8; i++) {
                int g = tid + i * 256;        // 0..2047
                int tile = g >> 10;
                int j = g & 1023;
                int row = j >> 3, seg = j & 7;
                uint32_t dst = st + tile * TILEB + SWZ128(row, seg);
                const char* src = pA[tile] + (size_t)row * (DIM * 2) + kb + seg * 16;
                CP_ASYNC16(dst, src);
            }
        };

        load_chunk(0, 0); CP_COMMIT();
        load_chunk(1, 1); CP_COMMIT();

        float acc[4][4][4];
#pragma unroll
        for (int i = 0; i < 4; i++)
#pragma unroll
            for (int j = 0; j < 4; j++)
#pragma unroll
                for (int q = 0; q < 4; q++) acc[i][j][q] = 0.f;

        for (int c = 0; c < NCHUNK; c++) {
            int s = c % STAGES;
            CP_WAIT1();                 // chunk c resident (c+1 still in flight)
            __syncthreads();            // WAR: all warps done with stage (c+2)%3
            if (c + 2 < NCHUNK) load_chunk(c + 2, (c + 2) % STAGES);
            CP_COMMIT();
            uint32_t st = tiles + s * STAGEB;
#pragma unroll
            for (int ks = 0; ks < 4; ks++) {
                int seg0 = ks * 2;
                uint32_t bH[4][2];
#pragma unroll
                for (int p = 0; p < 2; p++) {
                    int row = n_off + p * 16 + rowoff_b;
                    int seg = seg0 + segoff_b;
                    uint32_t bd = st + TILEB + SWZ128(row, seg);
                    uint32_t r[4];
                    LDSM_X4(r, bd);
                    bH[2 * p][0] = r[0]; bH[2 * p][1] = r[1];
                    bH[2 * p + 1][0] = r[2]; bH[2 * p + 1][1] = r[3];
                }
#pragma unroll
                for (int mt = 0; mt < 4; mt++) {
                    int row = m_off + mt * 16 + rowoff_a;
                    int seg = seg0 + segoff_a;
                    uint32_t ad = st + SWZ128(row, seg);
                    uint32_t aH[4];
                    LDSM_X4(aH, ad);
#pragma unroll
                    for (int nt = 0; nt < 4; nt++)
                        MMA_FP16(acc[mt][nt], aH, bH[nt]);
                }
            }
        }
        CP_WAIT0();                     // drain before smem reuse next iteration

        // ---- epilogue ----
        const int colb = bx * 128;
#pragma unroll
        for (int mt = 0; mt < 4; mt++) {
            size_t slot0 = rowA0 + m_off + mt * 16 + (lane >> 2);
            size_t slot1 = slot0 + 8;
            int tok0 = 0, tok1 = 0;
            float gt0 = 0.f, gt1 = 0.f;
            if (phase2) {
                tok0 = g_tok[slot0];
                tok1 = g_tok[slot1];
                gt0 = (tok0 >= 0) ? g_gate[tok0] : 0.f;
                gt1 = (tok1 >= 0) ? g_gate[tok1] : 0.f;
            }
#pragma unroll
            for (int nt = 0; nt < 4; nt++) {
                int cl = n_off + nt * 8 + 2 * (lane & 3);
                float b0 = sb[cl], b1v = sb[cl + 1];
                float v00 = acc[mt][nt][0] + b0, v01 = acc[mt][nt][1] + b1v;
                float v10 = acc[mt][nt][2] + b0, v11 = acc[mt][nt][3] + b1v;
                if (!phase2) {
                    v00 = fmaxf(v00, 0.f); v01 = fmaxf(v01, 0.f);
                    v10 = fmaxf(v10, 0.f); v11 = fmaxf(v11, 0.f);
                    *reinterpret_cast<uint32_t*>(g_Hh + slot0 * DIM + colb + cl) =
                        pk(__float2half_rn(v00), __float2half_rn(v01));
                    *reinterpret_cast<uint32_t*>(g_Hh + slot1 * DIM + colb + cl) =
                        pk(__float2half_rn(v10), __float2half_rn(v11));
                } else {
                    if (tok0 >= 0)
                        *reinterpret_cast<float2*>(out + (size_t)tok0 * DIM + colb + cl) =
                            make_float2(gt0 * v00, gt0 * v01);
                    if (tok1 >= 0)
                        *reinterpret_cast<float2*>(out + (size_t)tok1 * DIM + colb + cl) =
                            make_float2(gt1 * v10, gt1 * v11);
                }
            }
        }

        if (!phase2) {
            __threadfence();            // g_Hh stores visible before counter bump
            __syncthreads();            // all threads' stores issued
            if (tid == 0) atomicAdd(&g_done[ex], 1);
        }
    }
}

// ---------------- launch -------------------------------------------------------
extern "C" void kernel_launch(void* const* d_in, const int* in_sizes, int n_in,
                              void* d_out, int out_size) {
    const float* x  = (const float*)d_in[0];
    const float* Wr = (const float*)d_in[1];
    const float* br = (const float*)d_in[2];
    const float* W1 = (const float*)d_in[3];
    const float* b1 = (const float*)d_in[4];
    const float* W2 = (const float*)d_in[5];
    const float* b2 = (const float*)d_in[6];
    float* out = (float*)d_out;

    void *pB1h, *pB2h;
    cudaGetSymbolAddress(&pB1h, g_B1h);
    cudaGetSymbolAddress(&pB2h, g_B2h);

    cudaFuncSetAttribute(gemm_persist, cudaFuncAttributeMaxDynamicSharedMemorySize, GEMM_SMEM);

    // single side stream + 2 events (round-8 layout: verified delta=0)
    static cudaStream_t s_side = nullptr;
    static cudaEvent_t  ev_root = nullptr, ev_wt = nullptr;
    if (s_side == nullptr) {
        cudaStreamCreateWithFlags(&s_side, cudaStreamNonBlocking);
        cudaEventCreateWithFlags(&ev_root, cudaEventDisableTiming);
        cudaEventCreateWithFlags(&ev_wt,   cudaEventDisableTiming);
    }

    // fork: weight conversion runs concurrently with router/scan/dispatch
    cudaEventRecord(ev_root, 0);
    cudaStreamWaitEvent(s_side, ev_root, 0);
    dim3 wtg(16, 16, NEXP);
    wt_kernel<<<wtg, 256, 0, s_side>>>(W1, (__half*)pB1h);
    wt_kernel<<<wtg, 256, 0, s_side>>>(W2, (__half*)pB2h);
    cudaEventRecord(ev_wt, s_side);

    // main chain
    router_kernel<<<N_TOK * 32 / 256, 256>>>(x, Wr, br);
    scan_kernel<<<SCAN_BLOCKS, 1024>>>();
    dispatch_kernel<<<2 * NEXP * CAP, 256>>>(x, out);

    // join: GEMMs need converted weights
    cudaStreamWaitEvent(0, ev_wt, 0);

    gemm_persist<<<PERSIST_BLOCKS, 256, GEMM_SMEM>>>(
        (const __half*)pB1h, b1, (const __half*)pB2h, b2, out);
}

// round 15
// speedup vs baseline: 1.0563x; 1.0229x over previous
#include <cuda_runtime.h>
#include <cuda_fp16.h>
#include <cstdint>

#define N_TOK 8192
#define DIM   1024
#define NEXP  8
#define CAP   1024
#define SCAN_BLOCKS 8
#define TILES_PER_EXPERT 64   // 8x8 tiles of 128x128
#define G1_BLOCKS (NEXP * TILES_PER_EXPERT)
#define NDISP 512             // dispatch blocks, 16 slots each

// ---------------- scratch (device globals; no allocation allowed) ----------
__device__ __half g_Ah[(size_t)N_TOK * DIM];   // expert_in fp16
__device__ __half g_Hh[(size_t)N_TOK * DIM];   // hidden fp16
__device__ __half g_B1h[(size_t)N_TOK * DIM];  // W1^T fp16 [e][n][k]
__device__ __half g_B2h[(size_t)N_TOK * DIM];  // W2^T fp16
__device__ int   g_idx[N_TOK];
__device__ float g_gate[N_TOK];
__device__ int   g_comb[N_TOK];
__device__ int   g_tok[NEXP * CAP];
__device__ unsigned long long g_agg0[SCAN_BLOCKS], g_agg1[SCAN_BLOCKS];
__device__ int   g_flag[SCAN_BLOCKS];
__device__ int   g_sdone;                      // scan blocks completed
__device__ int   g_done[NEXP];                 // GEMM1 tile completion per expert

// ---------------- PTX helpers (sm_80-level only) -----------------------------
__device__ __forceinline__ uint32_t smem_u32(const void* p) {
    uint32_t a;
    asm("{ .reg .u64 t; cvta.to.shared.u64 t, %1; cvt.u32.u64 %0, t; }"
        : "=r"(a) : "l"(p));
    return a;
}

#define CP_ASYNC16(dst, src) \
    asm volatile("cp.async.cg.shared.global [%0], [%1], 16;" :: "r"(dst), "l"(src) : "memory")
#define CP_COMMIT() asm volatile("cp.async.commit_group;" ::: "memory")
#define CP_WAIT1()  asm volatile("cp.async.wait_group 1;" ::: "memory")

#define LDSM_X4(r, addr) \
    asm volatile("ldmatrix.sync.aligned.m8n8.x4.shared.b16 {%0,%1,%2,%3}, [%4];" \
        : "=r"((r)[0]), "=r"((r)[1]), "=r"((r)[2]), "=r"((r)[3]) : "r"(addr))

#define MMA_FP16(d, a, b) \
    asm volatile("mma.sync.aligned.m16n8k16.row.col.f32.f16.f16.f32 " \
        "{%0,%1,%2,%3}, {%4,%5,%6,%7}, {%8,%9}, {%0,%1,%2,%3};" \
        : "+f"((d)[0]), "+f"((d)[1]), "+f"((d)[2]), "+f"((d)[3]) \
        : "r"((a)[0]), "r"((a)[1]), "r"((a)[2]), "r"((a)[3]), \
          "r"((b)[0]), "r"((b)[1]))

__device__ __forceinline__ uint32_t pk(__half a, __half b) {
    return (uint32_t)__half_as_ushort(a) | ((uint32_t)__half_as_ushort(b) << 16);
}

// ---------------- router (+ counter/table init fused) ------------------------
__global__ void router_kernel(const float* __restrict__ x,
                              const float* __restrict__ Wr,
                              const float* __restrict__ br) {
    int gid = blockIdx.x * blockDim.x + threadIdx.x;
    if (gid < NEXP * CAP) g_tok[gid] = -1;
    if (gid < SCAN_BLOCKS) g_flag[gid] = 0;
    if (gid >= 8 && gid < 8 + NEXP) g_done[gid - 8] = 0;
    if (gid == 16) g_sdone = 0;
    int gwarp = gid >> 5;
    int lane  = threadIdx.x & 31;
    if (gwarp >= N_TOK) return;
    const float* xr = x + (size_t)gwarp * DIM;
    float acc[NEXP];
#pragma unroll
    for (int e = 0; e < NEXP; e++) acc[e] = 0.f;
    for (int d = lane; d < DIM; d += 32) {
        float xv = xr[d];
        const float* w = Wr + d * NEXP;
#pragma unroll
        for (int e = 0; e < NEXP; e++) acc[e] += xv * w[e];
    }
#pragma unroll
    for (int o = 16; o > 0; o >>= 1)
#pragma unroll
        for (int e = 0; e < NEXP; e++)
            acc[e] += __shfl_xor_sync(0xffffffffu, acc[e], o);
    if (lane == 0) {
        float m = -1e30f; int ai = 0;
#pragma unroll
        for (int e = 0; e < NEXP; e++) {
            acc[e] += br[e];
            if (acc[e] > m) { m = acc[e]; ai = e; }   // strict > keeps first
        }
        float s = 0.f;
#pragma unroll
        for (int e = 0; e < NEXP; e++) s += expf(acc[e] - m);
        g_idx[gwarp]  = ai;
        g_gate[gwarp] = 1.f / s;
    }
}

// ======== fused scan + dispatch (all light 256-thread blocks) =================
// bids [0,8):    scan, 4 tokens/thread, chained cross-block prefix
// bids [8,520):  dispatch 16 slots each + dropzero; spins g_sdone==8
// Spin targets strictly-lower bids; ascending-bid dispatch => deadlock-free.
__global__ void __launch_bounds__(256) sd_fused(const float* __restrict__ x,
                                                float* __restrict__ out) {
    const int tid = threadIdx.x;
    const int bid = blockIdx.x;

    if (bid < SCAN_BLOCKS) {
        __shared__ unsigned long long w0s[8], w1s[8];
        __shared__ unsigned long long prev0s, prev1s;
        int b = bid;
        int lane = tid & 31, wp = tid >> 5;   // 8 warps
        int4 v = reinterpret_cast<const int4*>(g_idx)[b * 256 + tid];
        int e4[4] = {v.x, v.y, v.z, v.w};
        unsigned long long c0 = 0ull, c1 = 0ull;
#pragma unroll
        for (int i = 0; i < 4; i++) {
            int e = e4[i];
            if (e < 4) c0 += 1ull << (16 * e);
            else       c1 += 1ull << (16 * (e - 4));
        }
        unsigned long long s0 = c0, s1 = c1;
#pragma unroll
        for (int o = 1; o < 32; o <<= 1) {
            unsigned long long t0 = __shfl_up_sync(0xffffffffu, s0, o);
            unsigned long long t1 = __shfl_up_sync(0xffffffffu, s1, o);
            if (lane >= o) { s0 += t0; s1 += t1; }
        }
        if (lane == 31) { w0s[wp] = s0; w1s[wp] = s1; }
        __syncthreads();
        if (tid == 0) {
            unsigned long long a0 = 0ull, a1 = 0ull;
#pragma unroll
            for (int w = 0; w < 8; w++) {       // exclusive warp prefixes + totals
                unsigned long long t0 = w0s[w], t1 = w1s[w];
                w0s[w] = a0; w1s[w] = a1;
                a0 += t0; a1 += t1;
            }
            unsigned long long p0 = 0ull, p1 = 0ull;
            if (b > 0) {
                while (atomicAdd(&g_flag[b - 1], 0) == 0) { }
                __threadfence();
                p0 = g_agg0[b - 1]; p1 = g_agg1[b - 1];
            }
            prev0s = p0; prev1s = p1;
            g_agg0[b] = p0 + a0; g_agg1[b] = p1 + a1;
            __threadfence();
            atomicExch(&g_flag[b], 1);
        }
        __syncthreads();
        unsigned long long p0 = prev0s + w0s[wp] + (s0 - c0);  // exclusive
        unsigned long long p1 = prev1s + w1s[wp] + (s1 - c1);
#pragma unroll
        for (int i = 0; i < 4; i++) {
            int n = b * 1024 + tid * 4 + i, e = e4[i];
            int pos;
            if (e < 4) { p0 += 1ull << (16 * e);       pos = (int)((p0 >> (16 * e)) & 0xFFFFull); }
            else       { p1 += 1ull << (16 * (e - 4)); pos = (int)((p1 >> (16 * (e - 4))) & 0xFFFFull); }
            if (pos < CAP) {
                g_comb[n] = e * CAP + pos;       // 1-based pos, slot 0 unused
                g_tok[e * CAP + pos] = n;
            } else {
                g_comb[n] = -1;
            }
        }
        __threadfence();
        __syncthreads();
        if (tid == 0) atomicAdd(&g_sdone, 1);
        return;
    }

    // ---- dispatch + dropzero ----
    int db = bid - SCAN_BLOCKS;      // 0..511
    if (tid == 0)
        while (atomicAdd(&g_sdone, 0) < SCAN_BLOCKS) { }
    __syncthreads();
    __threadfence();
#pragma unroll
    for (int i = 0; i < 16; i++) {
        int s = db * 16 + i;
        int n = g_tok[s];
        uint2* dh = reinterpret_cast<uint2*>(g_Ah + (size_t)s * DIM) + tid;
        if (n < 0) {
            *dh = make_uint2(0u, 0u);
        } else {
            float g = g_gate[n];
            float4 v = reinterpret_cast<const float4*>(x + (size_t)n * DIM)[tid];
            *dh = make_uint2(pk(__float2half_rn(v.x * g), __float2half_rn(v.y * g)),
                             pk(__float2half_rn(v.z * g), __float2half_rn(v.w * g)));
        }
    }
#pragma unroll
    for (int i = 0; i < 16; i++) {
        int n = db * 16 + i;
        if (g_comb[n] < 0)
            reinterpret_cast<float4*>(out + (size_t)n * DIM)[tid] =
                make_float4(0.f, 0.f, 0.f, 0.f);
    }
}

// -------- weight transpose fp32[k][n] -> fp16[n][k], both layers, one launch --
__global__ void __launch_bounds__(256) wt_kernel(const float* __restrict__ W1,
                                                 const float* __restrict__ W2,
                                                 __half* __restrict__ B1h,
                                                 __half* __restrict__ B2h) {
    __shared__ float ts[64][65];
    int z = blockIdx.z;
    const float* W = (z < NEXP) ? W1 : W2;
    __half* Bh     = (z < NEXP) ? B1h : B2h;
    int e = z & (NEXP - 1);
    int k0 = blockIdx.y * 64, n0 = blockIdx.x * 64;
    int t = threadIdx.x;
    const float* Wb = W + (size_t)e * DIM * DIM;
    int lr = t >> 4, lc = (t & 15) * 4;
#pragma unroll
    for (int i = 0; i < 4; i++) {
        int kr = lr + i * 16;
        float4 v = *reinterpret_cast<const float4*>(Wb + (size_t)(k0 + kr) * DIM + n0 + lc);
        ts[kr][lc + 0] = v.x; ts[kr][lc + 1] = v.y;
        ts[kr][lc + 2] = v.z; ts[kr][lc + 3] = v.w;
    }
    __syncthreads();
    int r  = t >> 2;             // n within tile
    int kk = (t & 3) * 16;       // k start
    uint32_t w[8];
#pragma unroll
    for (int q = 0; q < 8; q++)
        w[q] = pk(__float2half_rn(ts[kk + 2 * q][r]), __float2half_rn(ts[kk + 2 * q + 1][r]));
    size_t o = (size_t)e * DIM * DIM + (size_t)(n0 + r) * DIM + k0 + kk;
    *reinterpret_cast<uint4*>(Bh + o)     = make_uint4(w[0], w[1], w[2], w[3]);
    *reinterpret_cast<uint4*>(Bh + o + 8) = make_uint4(w[4], w[5], w[6], w[7]);
}

// -------- fused GEMM1+GEMM2 via mma.sync, device-side per-expert sync ---------
// (round-12 configuration — best measured)
#define STAGES  3
#define TILEB   16384             // 128 rows x 128B
#define NPLANES 2
#define STAGEB  (NPLANES * TILEB)
#define NCHUNK  16                // K=1024 / BK=64
#define GEMM_SMEM (2048 + STAGES * STAGEB)

// SW128 swizzle for 128B rows: seg(0..7) ^= row&7
#define SWZ128(row, seg) ((row) * 128 + (((seg) ^ ((row) & 7)) << 4))

__global__ void __launch_bounds__(256, 2) gemm_fused(
    const __half* __restrict__ B1h, const float* __restrict__ b1,
    const __half* __restrict__ B2h, const float* __restrict__ b2,
    float* __restrict__ out) {
    extern __shared__ char smem[];
    uint32_t raw = smem_u32(smem);
    uint32_t tiles = (raw + 512 + 1023) & ~1023u;
    float* sb = reinterpret_cast<float*>(smem + (tiles - 512 - raw)); // 128 floats

    const int tid = threadIdx.x;
    const int lane = tid & 31, wid = tid >> 5;
    const int bid = blockIdx.x;
    const bool phase2 = bid >= G1_BLOCKS;
    const int lb = phase2 ? bid - G1_BLOCKS : bid;
    const int ex = lb >> 6;
    const int tl = lb & 63;
    const int bx = tl & 7, by = tl >> 3;

    if (phase2) {
        if (tid == 0)
            while (atomicAdd(&g_done[ex], 0) < TILES_PER_EXPERT) { }
        __syncthreads();
        __threadfence();
    }

    const __half* Ain  = phase2 ? g_Hh : g_Ah;
    const __half* Bin  = phase2 ? B2h  : B1h;
    const float*  bias = phase2 ? b2   : b1;

    const size_t rowA0 = (size_t)ex * 1024 + (size_t)by * 128;
    const size_t rowB0 = (size_t)ex * 1024 + (size_t)bx * 128;
    const char* pA[2] = {
        (const char*)(Ain + rowA0 * DIM), (const char*)(Bin + rowB0 * DIM)};

    if (tid < 128) sb[tid] = bias[ex * DIM + bx * 128 + tid];

    auto load_chunk = [&](int c, int s) {
        uint32_t st = tiles + s * STAGEB;
        int kb = c * 128;  // 64 fp16 = 128B per row-chunk
#pragma unroll
        for (int i = 0; i < 8; i++) {
            int g = tid + i * 256;        // 0..2047
            int tile = g >> 10;
            int j = g & 1023;
            int row = j >> 3, seg = j & 7;
            uint32_t dst = st + tile * TILEB + SWZ128(row, seg);
            const char* src = pA[tile] + (size_t)row * (DIM * 2) + kb + seg * 16;
            CP_ASYNC16(dst, src);
        }
    };

    load_chunk(0, 0); CP_COMMIT();
    load_chunk(1, 1); CP_COMMIT();

    float acc[4][4][4];
#pragma unroll
    for (int i = 0; i < 4; i++)
#pragma unroll
        for (int j = 0; j < 4; j++)
#pragma unroll
            for (int q = 0; q < 4; q++) acc[i][j][q] = 0.f;

    const int m_off = (wid & 1) * 64;    // warp tile 64x32; warps 2x4
    const int n_off = (wid >> 1) * 32;
    const int grp = lane >> 3, loc = lane & 7;
    const int rowoff_a = (grp & 1) * 8 + loc;
    const int segoff_a = grp >> 1;
    const int rowoff_b = (grp >> 1) * 8 + loc;
    const int segoff_b = grp & 1;

    for (int c = 0; c < NCHUNK; c++) {
        int s = c % STAGES;
        CP_WAIT1();                 // chunk c resident (c+1 still in flight)
        __syncthreads();            // WAR: all warps done reading stage (c+2)%3
        if (c + 2 < NCHUNK) load_chunk(c + 2, (c + 2) % STAGES);
        CP_COMMIT();
        uint32_t st = tiles + s * STAGEB;
#pragma unroll
        for (int ks = 0; ks < 4; ks++) {
            int seg0 = ks * 2;
            uint32_t bH[4][2];
#pragma unroll
            for (int p = 0; p < 2; p++) {
                int row = n_off + p * 16 + rowoff_b;
                int seg = seg0 + segoff_b;
                uint32_t bd = st + TILEB + SWZ128(row, seg);
                uint32_t r[4];
                LDSM_X4(r, bd);
                bH[2 * p][0] = r[0]; bH[2 * p][1] = r[1];
                bH[2 * p + 1][0] = r[2]; bH[2 * p + 1][1] = r[3];
            }
#pragma unroll
            for (int mt = 0; mt < 4; mt++) {
                int row = m_off + mt * 16 + rowoff_a;
                int seg = seg0 + segoff_a;
                uint32_t ad = st + SWZ128(row, seg);
                uint32_t aH[4];
                LDSM_X4(aH, ad);
#pragma unroll
                for (int nt = 0; nt < 4; nt++)
                    MMA_FP16(acc[mt][nt], aH, bH[nt]);
            }
        }
    }

    // ---- epilogue ----
    const int colb = bx * 128;
#pragma unroll
    for (int mt = 0; mt < 4; mt++) {
        size_t slot0 = rowA0 + m_off + mt * 16 + (lane >> 2);
        size_t slot1 = slot0 + 8;
        int tok0 = 0, tok1 = 0;
        float gt0 = 0.f, gt1 = 0.f;
        if (phase2) {
            tok0 = g_tok[slot0];
            tok1 = g_tok[slot1];
            gt0 = (tok0 >= 0) ? g_gate[tok0] : 0.f;
            gt1 = (tok1 >= 0) ? g_gate[tok1] : 0.f;
        }
#pragma unroll
        for (int nt = 0; nt < 4; nt++) {
            int cl = n_off + nt * 8 + 2 * (lane & 3);
            float b0 = sb[cl], b1v = sb[cl + 1];
            float v00 = acc[mt][nt][0] + b0, v01 = acc[mt][nt][1] + b1v;
            float v10 = acc[mt][nt][2] + b0, v11 = acc[mt][nt][3] + b1v;
            if (!phase2) {
                v00 = fmaxf(v00, 0.f); v01 = fmaxf(v01, 0.f);
                v10 = fmaxf(v10, 0.f); v11 = fmaxf(v11, 0.f);
                *reinterpret_cast<uint32_t*>(g_Hh + slot0 * DIM + colb + cl) =
                    pk(__float2half_rn(v00), __float2half_rn(v01));
                *reinterpret_cast<uint32_t*>(g_Hh + slot1 * DIM + colb + cl) =
                    pk(__float2half_rn(v10), __float2half_rn(v11));
            } else {
                if (tok0 >= 0)
                    *reinterpret_cast<float2*>(out + (size_t)tok0 * DIM + colb + cl) =
                        make_float2(gt0 * v00, gt0 * v01);
                if (tok1 >= 0)
                    *reinterpret_cast<float2*>(out + (size_t)tok1 * DIM + colb + cl) =
                        make_float2(gt1 * v10, gt1 * v11);
            }
        }
    }

    if (!phase2) {
        __threadfence();            // g_Hh stores visible before counter bump
        __syncthreads();            // all threads' stores issued
        if (tid == 0) atomicAdd(&g_done[ex], 1);
    }
}

// ---------------- launch -------------------------------------------------------
extern "C" void kernel_launch(void* const* d_in, const int* in_sizes, int n_in,
                              void* d_out, int out_size) {
    const float* x  = (const float*)d_in[0];
    const float* Wr = (const float*)d_in[1];
    const float* br = (const float*)d_in[2];
    const float* W1 = (const float*)d_in[3];
    const float* b1 = (const float*)d_in[4];
    const float* W2 = (const float*)d_in[5];
    const float* b2 = (const float*)d_in[6];
    float* out = (float*)d_out;

    void *pB1h, *pB2h;
    cudaGetSymbolAddress(&pB1h, g_B1h);
    cudaGetSymbolAddress(&pB2h, g_B2h);

    cudaFuncSetAttribute(gemm_fused, cudaFuncAttributeMaxDynamicSharedMemorySize, GEMM_SMEM);

    // single side stream + 2 events (round-8 layout: verified delta=0)
    static cudaStream_t s_side = nullptr;
    static cudaEvent_t  ev_root = nullptr, ev_wt = nullptr;
    if (s_side == nullptr) {
        cudaStreamCreateWithFlags(&s_side, cudaStreamNonBlocking);
        cudaEventCreateWithFlags(&ev_root, cudaEventDisableTiming);
        cudaEventCreateWithFlags(&ev_wt,   cudaEventDisableTiming);
    }

    // fork: weight conversion (both layers, one launch) overlaps router/scan/dispatch
    cudaEventRecord(ev_root, 0);
    cudaStreamWaitEvent(s_side, ev_root, 0);
    dim3 wtg(16, 16, 2 * NEXP);
    wt_kernel<<<wtg, 256, 0, s_side>>>(W1, W2, (__half*)pB1h, (__half*)pB2h);
    cudaEventRecord(ev_wt, s_side);

    // main chain
    router_kernel<<<N_TOK * 32 / 256, 256>>>(x, Wr, br);
    sd_fused<<<SCAN_BLOCKS + NDISP, 256>>>(x, out);

    // join: GEMMs need converted weights
    cudaStreamWaitEvent(0, ev_wt, 0);

    gemm_fused<<<2 * G1_BLOCKS, 256, GEMM_SMEM>>>(
        (const __half*)pB1h, b1, (const __half*)pB2h, b2, out);
}